// round 17
// baseline (speedup 1.0000x reference)
#include <cuda_runtime.h>
#include <cuda_fp16.h>
#include <cstdint>

// Problem constants (fixed by the dataset)
#define NB 131072   // batch
#define ND 128      // input dim
#define NH 512      // hidden dim
#define NE 2        // experts
#define NO 2        // output dim

#define NCTA 148    // persistent grid
#define RB2  512    // route blocks (256 rows each)

// ---------------- scratch (device globals; no allocation allowed) ----------
__device__ int g_cnt[NE];        // zero at start; reset by mma at end of run
__device__ int g_done;           // arrival counter for end-of-run reset
__device__ int g_idx[NE][NB];
__device__ __align__(16) __half g_xh[(size_t)NB * 128];    // x fp16, 256B rows

// ---------------- helpers ---------------------------------------------------
__device__ __forceinline__ uint32_t smem_u32(const void* p) {
    uint32_t a;
    asm("{ .reg .u64 t; cvta.to.shared.u64 t, %1; cvt.u32.u64 %0, t; }"
        : "=r"(a) : "l"(p));
    return a;
}
__device__ __forceinline__ uint32_t f16x2(float a, float b) {
    uint32_t u;
    asm("cvt.rn.f16x2.f32 %0, %1, %2;" : "=r"(u) : "f"(b), "f"(a));
    return u;
}
__device__ __forceinline__ void ldsm4(uint32_t* r, uint32_t addr) {
    asm volatile("ldmatrix.sync.aligned.m8n8.x4.shared.b16 {%0,%1,%2,%3}, [%4];"
                 : "=r"(r[0]), "=r"(r[1]), "=r"(r[2]), "=r"(r[3]) : "r"(addr));
}
__device__ __forceinline__ void mma16816(float* d, const uint32_t* a,
                                         uint32_t b0, uint32_t b1) {
    asm volatile(
        "mma.sync.aligned.m16n8k16.row.col.f32.f16.f16.f32 "
        "{%0,%1,%2,%3}, {%4,%5,%6,%7}, {%8,%9}, {%0,%1,%2,%3};"
        : "+f"(d[0]), "+f"(d[1]), "+f"(d[2]), "+f"(d[3])
        : "r"(a[0]), "r"(a[1]), "r"(a[2]), "r"(a[3]), "r"(b0), "r"(b1));
}
__device__ __forceinline__ void cpasync16(uint32_t dst, const void* src) {
    asm volatile("cp.async.cg.shared.global [%0], [%1], 16;"
                 :: "r"(dst), "l"(src) : "memory");
}
#define CP_COMMIT() asm volatile("cp.async.commit_group;" ::: "memory")
#define CP_WAIT0()  asm volatile("cp.async.wait_group 0;" ::: "memory")

// ---------------- kernel 1: routing + x fp16 (barrier-free warps) ----------
// 512 blocks x 256 threads; each WARP autonomously handles 32 rows:
// distances + fp16 emit in one pass, per-warp atomic slot reservation,
// leader-lane scatter. No block barriers after the proto stage.
__global__ __launch_bounds__(256) void route_kernel(const float* __restrict__ x,
                                                    const float* __restrict__ protos) {
    __shared__ float ps[256];
    const int tid = threadIdx.x;
    ps[tid] = protos[tid];
    __syncthreads();

    const int l  = tid & 31, wd = tid >> 5;
    const int q  = l >> 2;          // quad id: row within group of 8
    const int j4 = l & 3;           // lane within quad
    const int wbase = (blockIdx.x * 8 + wd) * 32;   // 32 rows per warp

    const float4* p0 = reinterpret_cast<const float4*>(ps);
    const float4* p1 = p0 + 32;

    unsigned m_e[4];
    #pragma unroll
    for (int i = 0; i < 4; i++) {
        const int row = wbase + i * 8 + q;
        const float4* xr = reinterpret_cast<const float4*>(x) + (size_t)row * 32;
        uint2* xo = reinterpret_cast<uint2*>(g_xh) + (size_t)row * 32;
        float d0 = 0.f, d1 = 0.f;
        #pragma unroll
        for (int c = 0; c < 8; c++) {
            float4 v = xr[j4 + c * 4];
            float4 a = p0[j4 + c * 4];
            float4 b = p1[j4 + c * 4];
            float t;
            t = v.x - a.x; d0 += t * t;   t = v.y - a.y; d0 += t * t;
            t = v.z - a.z; d0 += t * t;   t = v.w - a.w; d0 += t * t;
            t = v.x - b.x; d1 += t * t;   t = v.y - b.y; d1 += t * t;
            t = v.z - b.z; d1 += t * t;   t = v.w - b.w; d1 += t * t;
            xo[j4 + c * 4] = make_uint2(f16x2(v.x, v.y), f16x2(v.z, v.w));
        }
        d0 += __shfl_xor_sync(0xffffffffu, d0, 1);
        d0 += __shfl_xor_sync(0xffffffffu, d0, 2);
        d1 += __shfl_xor_sync(0xffffffffu, d1, 1);
        d1 += __shfl_xor_sync(0xffffffffu, d1, 2);
        const int er = (d1 < d0) ? 1 : 0;          // tie -> 0 (argmin first)
        m_e[i] = __ballot_sync(0xffffffffu, (j4 == 0) && er);
    }

    int k1 = 0;
    #pragma unroll
    for (int i = 0; i < 4; i++) k1 += __popc(m_e[i]);

    // per-warp slot reservation (no block barrier)
    int b0 = 0, b1r = 0;
    if (l == 0) {
        b0  = atomicAdd(&g_cnt[0], 32 - k1);
        b1r = atomicAdd(&g_cnt[1], k1);
    }
    b0  = __shfl_sync(0xffffffffu, b0, 0);
    b1r = __shfl_sync(0xffffffffu, b1r, 0);

    if (j4 == 0) {                  // 8 leader lanes scatter the warp's rows
        const unsigned lowmask = (1u << l) - 1u;
        int run0 = 0, run1 = 0;
        #pragma unroll
        for (int i = 0; i < 4; i++) {
            const int cnt1 = __popc(m_e[i]);
            const int ei   = (m_e[i] >> l) & 1;
            const int lo1  = __popc(m_e[i] & lowmask);
            const int lo0  = q - lo1;
            const int slot = ei ? (b1r + run1 + lo1) : (b0 + run0 + lo0);
            g_idx[ei][slot] = wbase + i * 8 + q;
            run1 += cnt1;
            run0 += 8 - cnt1;
        }
    }
}

// ---------------- kernel 2: persistent HMMA GEMM + fused epilogue ----------
// Main loop UNCHANGED from the 82.7us best (8 warps = 4m x 2n, m32 x n64).
// Prologue now converts W1 fp32 -> fp16 directly into smem (no g_w1c).
#define PITCH 272
#define ABUF  (128 * PITCH)                 // 34816
#define SM_W    0                           // 512 rows -> 139264
#define SM_A    (512 * PITCH)               // 139264, 2 bufs
#define SM_B1   (SM_A + 2 * ABUF)           // 208896
#define SM_W20  (SM_B1 + 2048)              // 210944
#define SM_W21  (SM_W20 + 2048)             // 212992
#define SM_OUT  (SM_W21 + 2048)             // 215040  128*2 floats
#define SM_HDR  (SM_OUT + 1024)             // 216064
#define SM_TOTAL (SM_HDR + 64)              // 216128 bytes

extern __shared__ __align__(1024) unsigned char sm_mma[];

__global__ __launch_bounds__(256, 1) void mma_kernel(
    const float* __restrict__ w1, const float* __restrict__ b1,
    const float* __restrict__ w2, const float* __restrict__ b2,
    float* __restrict__ out) {

    const int tid = threadIdx.x;
    int* hdr = (int*)(sm_mma + SM_HDR);

    // read counts once; end-of-run reset by the last arriving CTA
    if (tid == 0) {
        int c0 = g_cnt[0], c1 = g_cnt[1];
        hdr[0] = c0; hdr[1] = c1;
        unsigned dep = ((unsigned)(c0 | c1)) >> 31;     // 0, but data-dependent
        int old = atomicAdd(&g_done, 1 + (int)dep);
        if (old == NCTA - 1) { g_cnt[0] = 0; g_cnt[1] = 0; g_done = 0; }
    }
    __syncthreads();
    const int c0 = hdr[0], c1 = hdr[1];

    const int t0 = (c0 + 127) >> 7, t1 = (c1 + 127) >> 7;
    const int T = t0 + t1;
    int n0c;
    if (t1 == 0)      n0c = NCTA;
    else if (t0 == 0) n0c = 0;
    else {
        n0c = (int)((long long)NCTA * t0 / T);
        if (n0c < 1) n0c = 1;
        if (n0c > NCTA - 1) n0c = NCTA - 1;
    }

    int e, tbase, tstride, tcnt, cnt;
    if ((int)blockIdx.x < n0c) { e = 0; tbase = blockIdx.x;        tstride = n0c;        tcnt = t0; cnt = c0; }
    else                       { e = 1; tbase = blockIdx.x - n0c;  tstride = NCTA - n0c; tcnt = t1; cnt = c1; }
    const int ntiles = (tbase < tcnt) ? (tcnt - 1 - tbase) / tstride + 1 : 0;
    if (ntiles == 0) return;

    const uint32_t smb = smem_u32(sm_mma);
    float* b1s  = (float*)(sm_mma + SM_B1);
    float* w20  = (float*)(sm_mma + SM_W20);
    float* w21  = (float*)(sm_mma + SM_W21);
    float* outb = (float*)(sm_mma + SM_OUT);

    // ---- A-tile prefetch: 256B fp16 rows from g_xh, 2 threads per row ------
    auto prefetchA = [&](int posbase, int buf) {
        const int row = tid >> 1, segb = (tid & 1) * 8;
        int pos = posbase + row;
        int gi = g_idx[e][(pos < cnt) ? pos : posbase];
        const char* src = (const char*)g_xh + (size_t)gi * 256 + segb * 16;
        uint32_t dst = smb + SM_A + buf * ABUF + row * PITCH + segb * 16;
        #pragma unroll
        for (int j = 0; j < 8; j++) cpasync16(dst + j * 16, src + j * 16);
        CP_COMMIT();
    };

    // ---- prologue: A(tile0) cp.async + W1 fp32->fp16 into smem + coeffs ----
    prefetchA(tbase * 128, 0);
    {
        // W1[e] is NH x ND fp32 = NH x 32 float4; convert to fp16 rows of 256B
        const float4* wsrc = (const float4*)w1 + (size_t)e * NH * 32;
        for (int i = tid; i < NH * 32; i += 256) {
            float4 v = wsrc[i];
            int row = i >> 5, c4 = i & 31;
            *(uint2*)(sm_mma + SM_W + row * PITCH + c4 * 8) =
                make_uint2(f16x2(v.x, v.y), f16x2(v.z, v.w));
        }
    }
    for (int i = tid; i < NH; i += 256) {
        b1s[i] = b1[e * NH + i];
        w20[i] = w2[(e * NO + 0) * NH + i];
        w21[i] = w2[(e * NO + 1) * NH + i];
    }
    outb[tid] = 0.f;
    const float b2e0 = b2[e * NO + 0], b2e1 = b2[e * NO + 1];

    CP_WAIT0();
    __syncthreads();

    // ---- per-lane fragment addressing (4m x 2n, warp tile m32 x n64) -------
    const int l  = tid & 31;
    const int w  = tid >> 5;
    const int wm = w & 3;       // m group (32 rows)
    const int wn = w >> 2;      // n half (64 cols)

    uint32_t aRel0, aRel1;
    {
        int mrow = wm * 32 + (l & 7) + ((l >> 3) & 1) * 8;
        int koff = (l >= 16) ? 16 : 0;
        aRel0 = (uint32_t)(mrow * PITCH + koff);
        aRel1 = aRel0 + 16 * PITCH;
    }
    uint32_t bOff[4];
    {
        int nr   = (l & 7) + ((l >= 16) ? 8 : 0);
        int koff = ((l >> 3) & 1) * 16;
        #pragma unroll
        for (int nj = 0; nj < 4; nj++)
            bOff[nj] = (uint32_t)((wn * 64 + nj * 16 + nr) * PITCH + koff);
    }

    // ---- persistent tile loop ----------------------------------------------
    int p = 0;
    for (int it = 0; it < ntiles; it++) {
        const int posbase = (tbase + it * tstride) * 128;
        if (it + 1 < ntiles) prefetchA((tbase + (it + 1) * tstride) * 128, p ^ 1);

        // A fragments: m32 x k128, loaded once, reused across all 4 n-passes
        const uint32_t abase = smb + SM_A + p * ABUF;
        uint32_t areg[8][2][4];
        #pragma unroll
        for (int ks = 0; ks < 8; ks++) {
            ldsm4(areg[ks][0], abase + aRel0 + ks * 32);
            ldsm4(areg[ks][1], abase + aRel1 + ks * 32);
        }

        float o0[4] = {0.f, 0.f, 0.f, 0.f};
        float o1[4] = {0.f, 0.f, 0.f, 0.f};

        #pragma unroll
        for (int nt = 0; nt < 4; nt++) {
            float acc[2][8][4];
            #pragma unroll
            for (int mi = 0; mi < 2; mi++)
                #pragma unroll
                for (int ni = 0; ni < 8; ni++)
                    #pragma unroll
                    for (int c = 0; c < 4; c++) acc[mi][ni][c] = 0.f;

            const uint32_t wbase = smb + SM_W + nt * 128 * PITCH;
            #pragma unroll
            for (int ks = 0; ks < 8; ks++) {
                const int off = ks * 32;
                uint32_t b[4][4];
                #pragma unroll
                for (int nj = 0; nj < 4; nj++)
                    ldsm4(b[nj], wbase + bOff[nj] + off);
                #pragma unroll
                for (int mi = 0; mi < 2; mi++)
                    #pragma unroll
                    for (int nj = 0; nj < 4; nj++) {
                        mma16816(acc[mi][2 * nj],     areg[ks][mi], b[nj][0], b[nj][1]);
                        mma16816(acc[mi][2 * nj + 1], areg[ks][mi], b[nj][2], b[nj][3]);
                    }
            }

            // fused epilogue: +b1, relu, *W2 -> per-lane partials (no barrier)
            const int hbase = nt * 128 + wn * 64 + 2 * (l & 3);
            #pragma unroll
            for (int ni = 0; ni < 8; ni++) {
                const int h = hbase + ni * 8;
                float bq0 = b1s[h],   bq1 = b1s[h + 1];
                float p00 = w20[h],   p01 = w20[h + 1];
                float p10 = w21[h],   p11 = w21[h + 1];
                #pragma unroll
                for (int mi = 0; mi < 2; mi++)
                    #pragma unroll
                    for (int c = 0; c < 4; c++) {
                        float v = acc[mi][ni][c] + ((c & 1) ? bq1 : bq0);
                        v = fmaxf(v, 0.f);
                        int s = mi * 2 + (c >> 1);
                        o0[s] = fmaf(v, (c & 1) ? p01 : p00, o0[s]);
                        o1[s] = fmaf(v, (c & 1) ? p11 : p10, o1[s]);
                    }
            }
        }

        // quad reduce (cols live on l&3), cross-n-warp via smem atomics
        #pragma unroll
        for (int s = 0; s < 4; s++) {
            o0[s] += __shfl_xor_sync(0xffffffffu, o0[s], 1);
            o0[s] += __shfl_xor_sync(0xffffffffu, o0[s], 2);
            o1[s] += __shfl_xor_sync(0xffffffffu, o1[s], 1);
            o1[s] += __shfl_xor_sync(0xffffffffu, o1[s], 2);
        }
        if ((l & 3) == 0) {
            #pragma unroll
            for (int s = 0; s < 4; s++) {
                int row = wm * 32 + (s >> 1) * 16 + (s & 1) * 8 + (l >> 2);
                atomicAdd(&outb[row * 2 + 0], o0[s]);
                atomicAdd(&outb[row * 2 + 1], o1[s]);
            }
        }
        __syncthreads();

        if (tid < 128) {
            int pos = posbase + tid;
            if (pos < cnt) {
                int gi = g_idx[e][pos];
                out[(size_t)gi * 2 + 0] = outb[tid * 2 + 0] + b2e0;
                out[(size_t)gi * 2 + 1] = outb[tid * 2 + 1] + b2e1;
            }
            outb[tid * 2 + 0] = 0.f;     // reader zeroes what it read (no race)
            outb[tid * 2 + 1] = 0.f;
        }

        CP_WAIT0();          // next A tile resident
        __syncthreads();     // outb reset + A buffer handoff visible to all
        p ^= 1;
    }
}

// ---------------- launch ----------------------------------------------------
extern "C" void kernel_launch(void* const* d_in, const int* in_sizes, int n_in,
                              void* d_out, int out_size) {
    const float* x      = (const float*)d_in[0];
    const float* w1     = (const float*)d_in[1];
    const float* b1     = (const float*)d_in[2];
    const float* w2     = (const float*)d_in[3];
    const float* b2     = (const float*)d_in[4];
    const float* protos = (const float*)d_in[5];
    float* out = (float*)d_out;

    static int smem_set = 0;
    if (!smem_set) {
        cudaFuncSetAttribute(mma_kernel, cudaFuncAttributeMaxDynamicSharedMemorySize,
                             SM_TOTAL);
        smem_set = 1;
    }

    route_kernel<<<RB2, 256>>>(x, protos);
    mma_kernel<<<NCTA, 256, SM_TOTAL>>>(w1, b1, w2, b2, out);
}